// round 11
// baseline (speedup 1.0000x reference)
#include <cuda_runtime.h>
#include <cuda_fp16.h>
#include <cstdint>

// ---------------------------------------------------------------------------
// Neural-SDF ray march + tube min + reflectance.
// Warp-cooperative, 16 rays/warp (M=16): each SDF eval = 16x128x128 GEMM via
// mma.sync.m16n8k16 f16 (128 mma). C-fragment = 64 regs -> 4 blocks/SM
// (16 warps/SM) to keep the legacy HMMA pipe fed.
//   * march + tube scan: 1-term fp16
//   * column-3: ONE precise fp16 3-term eval per ray at the approx argmin;
//     B_lo residuals streamed from a __device__ global (L2-resident)
//   * B fp16 pre-packed in fragment order by a prep kernel
// ---------------------------------------------------------------------------

#define DINL __device__ __forceinline__

namespace {
constexpr int   HN     = 128;
constexpr float kNEAR  = 0.2f;
constexpr float kFAR   = 2.0f;
constexpr float kALPHA = 100.0f;
constexpr float kEPS   = 0.005f;
constexpr int   kITERS = 32;
constexpr int   kTP    = 32;
constexpr float kSTEP  = 0.0634765625f;  // (2 + 0.5*(2/32))/32, exact fp32

// shared memory layout (float offsets)
constexpr int OFF_BH   = 0;        // 8192 floats: W2 fp16-hi, float4 = 2 n-blocks
constexpr int OFF_W1   = 8192;     // float4[128]: (W1[0][k],W1[1][k],W1[2][k],b1[k])
constexpr int OFF_BW   = 8704;     // float4[64]->(b2[n],W3[n],b2[n+1],W3[n+1]) x128
constexpr int OFF_R1A  = 9216;     // float4[128]: R1 rows 0..3
constexpr int OFF_R1B  = 9728;     // float4[128]: (R1[4][j],R1[5][j],rb1[j],0)
constexpr int OFF_R2   = 10240;    // float4[128]: (R2[j][0..2],0)
constexpr int OFF_MISC = 10752;    // rb2[0..2], b3
constexpr int SMEM_FLOATS = 10756;
constexpr int SMEM_BYTES  = SMEM_FLOATS * 4;
}  // namespace

// W2 fp16 hi/lo in mma-fragment pack, staged once by prep kernel.
__device__ float4 g_BH[2048];
__device__ float4 g_BL[2048];

// ----------------------------- helpers --------------------------------------
DINL uint32_t pk16(float e0, float e1) {   // low = rn(e0), high = rn(e1)
    uint32_t d;
    asm("cvt.rn.f16x2.f32 %0, %1, %2;" : "=r"(d) : "f"(e1), "f"(e0));
    return d;
}
DINL uint32_t pk16relu(float e0, float e1) {
    uint32_t d;
    asm("cvt.rn.relu.f16x2.f32 %0, %1, %2;" : "=r"(d) : "f"(e1), "f"(e0));
    return d;
}
DINL float f16_round(float x) { return __half2float(__float2half_rn(x)); }

// ----------------------------- mma wrappers ---------------------------------
DINL void mma16_acc(float c[4], uint32_t a0, uint32_t a1, uint32_t a2,
                    uint32_t a3, uint32_t b0, uint32_t b1) {
    asm volatile(
        "mma.sync.aligned.m16n8k16.row.col.f32.f16.f16.f32 "
        "{%0,%1,%2,%3},{%4,%5,%6,%7},{%8,%9},{%0,%1,%2,%3};"
        : "+f"(c[0]), "+f"(c[1]), "+f"(c[2]), "+f"(c[3])
        : "r"(a0), "r"(a1), "r"(a2), "r"(a3), "r"(b0), "r"(b1));
}
DINL void mma16_zero(float c[4], uint32_t a0, uint32_t a1, uint32_t a2,
                     uint32_t a3, uint32_t b0, uint32_t b1) {
    float z = 0.0f;
    asm volatile(
        "mma.sync.aligned.m16n8k16.row.col.f32.f16.f16.f32 "
        "{%0,%1,%2,%3},{%4,%5,%6,%7},{%8,%9},{%10,%10,%10,%10};"
        : "=f"(c[0]), "=f"(c[1]), "=f"(c[2]), "=f"(c[3])
        : "r"(a0), "r"(a1), "r"(a2), "r"(a3), "r"(b0), "r"(b1), "f"(z));
}

// ---- layer-1 A fragment for k-chunk kc (M=16; rays = A rows) ----------------
// lane (q=lane>>2, t=lane&3) holds k0=16kc+2t{,+1,+8,+9} for rows q (ray XA)
// and q+8 (ray XB):  a0=(q:k0,k0+1) a1=(q+8:k0,k0+1) a2=(q:k0+8,k0+9) a3=(q+8:..)
DINL void l1_frag(int kc, int t4, const float XA[3], const float XB[3],
                  const float4* __restrict__ w1pack, uint32_t a[4],
                  float hv[8]) {
    const int k0 = kc * 16 + 2 * t4;
    float4 w0 = w1pack[k0];
    float4 w1 = w1pack[k0 + 1];
    float4 w8 = w1pack[k0 + 8];
    float4 w9 = w1pack[k0 + 9];
    hv[0] = fmaf(w0.x, XA[0], fmaf(w0.y, XA[1], fmaf(w0.z, XA[2], w0.w)));
    hv[1] = fmaf(w1.x, XA[0], fmaf(w1.y, XA[1], fmaf(w1.z, XA[2], w1.w)));
    hv[2] = fmaf(w0.x, XB[0], fmaf(w0.y, XB[1], fmaf(w0.z, XB[2], w0.w)));
    hv[3] = fmaf(w1.x, XB[0], fmaf(w1.y, XB[1], fmaf(w1.z, XB[2], w1.w)));
    hv[4] = fmaf(w8.x, XA[0], fmaf(w8.y, XA[1], fmaf(w8.z, XA[2], w8.w)));
    hv[5] = fmaf(w9.x, XA[0], fmaf(w9.y, XA[1], fmaf(w9.z, XA[2], w9.w)));
    hv[6] = fmaf(w8.x, XB[0], fmaf(w8.y, XB[1], fmaf(w8.z, XB[2], w8.w)));
    hv[7] = fmaf(w9.x, XB[0], fmaf(w9.y, XB[1], fmaf(w9.z, XB[2], w9.w)));
    a[0] = pk16relu(hv[0], hv[1]);
    a[1] = pk16relu(hv[2], hv[3]);
    a[2] = pk16relu(hv[4], hv[5]);
    a[3] = pk16relu(hv[6], hv[7]);
}

// ---- epilogue: p[r] = sum_n relu(C(r,n)+b2[n])*W3[n]; own-ray value ---------
DINL float epi_reduce(const float C[16][4], const float4* __restrict__ bwv,
                      int lane) {
    const int t4 = lane & 3;
    float pq = 0.f, pq8 = 0.f;
#pragma unroll
    for (int nb = 0; nb < 16; ++nb) {
        float4 bw = bwv[nb * 4 + t4];  // (b2[n],W3[n],b2[n+1],W3[n+1]), n=8nb+2t
        pq  = fmaf(fmaxf(C[nb][0] + bw.x, 0.f), bw.y, pq);
        pq  = fmaf(fmaxf(C[nb][1] + bw.z, 0.f), bw.w, pq);
        pq8 = fmaf(fmaxf(C[nb][2] + bw.x, 0.f), bw.y, pq8);
        pq8 = fmaf(fmaxf(C[nb][3] + bw.z, 0.f), bw.w, pq8);
    }
    pq  += __shfl_xor_sync(0xffffffffu, pq, 1);
    pq  += __shfl_xor_sync(0xffffffffu, pq, 2);
    pq8 += __shfl_xor_sync(0xffffffffu, pq8, 1);
    pq8 += __shfl_xor_sync(0xffffffffu, pq8, 2);
    // ray rl = lane&15: row rl<8 -> pq from quad rl; else pq8 from quad rl-8
    int src = (lane & 7) << 2;
    float v1 = __shfl_sync(0xffffffffu, pq, src);
    float v2 = __shfl_sync(0xffffffffu, pq8, src);
    return ((lane & 15) < 8) ? v1 : v2;
}

// --------------------- approx eval: 1-term fp16 (128 mma) --------------------
DINL float sdf_approx(const float XA[3], const float XB[3],
                      const float4* __restrict__ w1pack,
                      const float4* __restrict__ sBH,
                      const float4* __restrict__ bwv, int lane) {
    const int t4 = lane & 3;
    float C[16][4];
#pragma unroll
    for (int kc = 0; kc < 8; ++kc) {
        uint32_t a[4];
        float hv[8];
        l1_frag(kc, t4, XA, XB, w1pack, a, hv);
        const float4* bq = sBH + kc * 256 + lane;
#pragma unroll
        for (int nbp = 0; nbp < 8; ++nbp) {
            float4 B = bq[nbp * 32];
            uint32_t b0 = __float_as_uint(B.x), b1 = __float_as_uint(B.y);
            uint32_t b2r = __float_as_uint(B.z), b3r = __float_as_uint(B.w);
            if (kc == 0) {
                mma16_zero(C[2 * nbp],     a[0], a[1], a[2], a[3], b0, b1);
                mma16_zero(C[2 * nbp + 1], a[0], a[1], a[2], a[3], b2r, b3r);
            } else {
                mma16_acc(C[2 * nbp],     a[0], a[1], a[2], a[3], b0, b1);
                mma16_acc(C[2 * nbp + 1], a[0], a[1], a[2], a[3], b2r, b3r);
            }
        }
    }
    return epi_reduce(C, bwv, lane);
}

// --------------- precise eval: 3-term fp16 (384 mma, once per ray) -----------
DINL float sdf_precise(const float XA[3], const float XB[3],
                       const float4* __restrict__ w1pack,
                       const float4* __restrict__ sBH,
                       const float4* __restrict__ bwv, int lane) {
    const int t4 = lane & 3;
    float C[16][4];
#pragma unroll 1
    for (int kc = 0; kc < 8; ++kc) {
        uint32_t ahi[4], alo[4];
        float hv[8];
        l1_frag(kc, t4, XA, XB, w1pack, ahi, hv);
        // residuals of the relu'd values (relu(h) - f16(relu(h)))
        float r[8];
#pragma unroll
        for (int s = 0; s < 8; ++s) {
            float h = fmaxf(hv[s], 0.f);
            r[s] = h - f16_round(h);
        }
        alo[0] = pk16(r[0], r[1]);
        alo[1] = pk16(r[2], r[3]);
        alo[2] = pk16(r[4], r[5]);
        alo[3] = pk16(r[6], r[7]);
        const float4* bqh = sBH + kc * 256 + lane;
        const float4* bql = g_BL + kc * 256 + lane;
#pragma unroll
        for (int nbp = 0; nbp < 8; ++nbp) {
            float4 BH = bqh[nbp * 32];
            float4 BL = bql[nbp * 32];
            uint32_t h0 = __float_as_uint(BH.x), h1 = __float_as_uint(BH.y);
            uint32_t h2 = __float_as_uint(BH.z), h3 = __float_as_uint(BH.w);
            uint32_t l0 = __float_as_uint(BL.x), l1 = __float_as_uint(BL.y);
            uint32_t l2 = __float_as_uint(BL.z), l3 = __float_as_uint(BL.w);
            if (kc == 0) {
                mma16_zero(C[2 * nbp],     ahi[0], ahi[1], ahi[2], ahi[3], h0, h1);
                mma16_zero(C[2 * nbp + 1], ahi[0], ahi[1], ahi[2], ahi[3], h2, h3);
            } else {
                mma16_acc(C[2 * nbp],     ahi[0], ahi[1], ahi[2], ahi[3], h0, h1);
                mma16_acc(C[2 * nbp + 1], ahi[0], ahi[1], ahi[2], ahi[3], h2, h3);
            }
            mma16_acc(C[2 * nbp],     alo[0], alo[1], alo[2], alo[3], h0, h1);
            mma16_acc(C[2 * nbp + 1], alo[0], alo[1], alo[2], alo[3], h2, h3);
            mma16_acc(C[2 * nbp],     ahi[0], ahi[1], ahi[2], ahi[3], l0, l1);
            mma16_acc(C[2 * nbp + 1], ahi[0], ahi[1], ahi[2], ahi[3], l2, l3);
        }
    }
    return epi_reduce(C, bwv, lane);
}

// own coords -> A-row coords: XA = ray (lane>>2), XB = ray (lane>>2)+8
DINL void bcast2(float x0, float x1, float x2, int lane,
                 float XA[3], float XB[3]) {
    int q = (lane >> 2) & 7;
    XA[0] = __shfl_sync(0xffffffffu, x0, q);
    XA[1] = __shfl_sync(0xffffffffu, x1, q);
    XA[2] = __shfl_sync(0xffffffffu, x2, q);
    XB[0] = __shfl_sync(0xffffffffu, x0, q + 8);
    XB[1] = __shfl_sync(0xffffffffu, x1, q + 8);
    XB[2] = __shfl_sync(0xffffffffu, x2, q + 8);
}

// ------------------------- prep kernel (B pack) -------------------------------
// entry idx: (kc*8 + nbp)*32 + l; t=l&3, g=l>>2, k0=16kc+2t, n0=16nbp+g, n1=n0+8
__global__ void sdf_prep_kernel(const float* __restrict__ W2) {
    int idx = blockIdx.x * blockDim.x + threadIdx.x;
    if (idx >= 2048) return;
    int l = idx & 31, nbp = (idx >> 5) & 7, kc = idx >> 8;
    int t = l & 3, g = l >> 2;
    int n0 = nbp * 16 + g, n1 = n0 + 8;
    int k0 = kc * 16 + 2 * t;
    float a00 = W2[k0 * HN + n0],       a01 = W2[(k0 + 1) * HN + n0];
    float a08 = W2[(k0 + 8) * HN + n0], a09 = W2[(k0 + 9) * HN + n0];
    float b00 = W2[k0 * HN + n1],       b01 = W2[(k0 + 1) * HN + n1];
    float b08 = W2[(k0 + 8) * HN + n1], b09 = W2[(k0 + 9) * HN + n1];
    float4 vh, vl;
    vh.x = __uint_as_float(pk16(a00, a01));
    vh.y = __uint_as_float(pk16(a08, a09));
    vh.z = __uint_as_float(pk16(b00, b01));
    vh.w = __uint_as_float(pk16(b08, b09));
    vl.x = __uint_as_float(pk16(a00 - f16_round(a00), a01 - f16_round(a01)));
    vl.y = __uint_as_float(pk16(a08 - f16_round(a08), a09 - f16_round(a09)));
    vl.z = __uint_as_float(pk16(b00 - f16_round(b00), b01 - f16_round(b01)));
    vl.w = __uint_as_float(pk16(b08 - f16_round(b08), b09 - f16_round(b09)));
    g_BH[idx] = vh;
    g_BL[idx] = vl;
}

// ------------------------------- main kernel ---------------------------------
__global__ void __launch_bounds__(128, 4) sdf_mma_kernel(
    const float* __restrict__ rays,
    const float* __restrict__ W1, const float* __restrict__ b1,
    const float* __restrict__ b2,
    const float* __restrict__ W3, const float* __restrict__ b3,
    const float* __restrict__ R1, const float* __restrict__ rb1,
    const float* __restrict__ R2, const float* __restrict__ rb2,
    float* __restrict__ out, int n)
{
    extern __shared__ float smem[];
    const int tid = threadIdx.x;
    const int lane = tid & 31;
    const int wid = tid >> 5;

    // ---- copy pre-packed B_hi into smem ----
    {
        float4* dst = reinterpret_cast<float4*>(smem + OFF_BH);
        for (int i = tid; i < 2048; i += 128) dst[i] = g_BH[i];
    }
    // ---- small weights ----
    {
        float4* w1v  = reinterpret_cast<float4*>(smem + OFF_W1);
        float2* bwv2 = reinterpret_cast<float2*>(smem + OFF_BW);
        float4* r1av = reinterpret_cast<float4*>(smem + OFF_R1A);
        float4* r1bv = reinterpret_cast<float4*>(smem + OFF_R1B);
        float4* r2v  = reinterpret_cast<float4*>(smem + OFF_R2);
        for (int j = tid; j < HN; j += 128) {
            w1v[j]  = make_float4(W1[j], W1[HN + j], W1[2 * HN + j], b1[j]);
            bwv2[j] = make_float2(b2[j], W3[j]);
            r1av[j] = make_float4(R1[j], R1[HN + j], R1[2 * HN + j], R1[3 * HN + j]);
            r1bv[j] = make_float4(R1[4 * HN + j], R1[5 * HN + j], rb1[j], 0.0f);
            r2v[j]  = make_float4(R2[3 * j], R2[3 * j + 1], R2[3 * j + 2], 0.0f);
        }
    }
    if (tid < 3) smem[OFF_MISC + tid] = rb2[tid];
    if (tid == 0) smem[OFF_MISC + 3] = b3[0];
    __syncthreads();

    const float4* w1pack = reinterpret_cast<const float4*>(smem + OFF_W1);
    const float4* sBH    = reinterpret_cast<const float4*>(smem + OFF_BH);
    const float4* bwv    = reinterpret_cast<const float4*>(smem + OFF_BW);
    const float bb3 = smem[OFF_MISC + 3];

    // 16 rays per warp; lanes 16..31 mirror lanes 0..15
    const int rl = lane & 15;
    int ray = blockIdx.x * 64 + wid * 16 + rl;
    const bool active = (ray < n) && (lane < 16);
    if (ray >= n) ray = n - 1;
    const float ro0 = rays[ray * 6 + 0], ro1 = rays[ray * 6 + 1], ro2 = rays[ray * 6 + 2];
    const float rd0 = rays[ray * 6 + 3], rd1 = rays[ray * 6 + 4], rd2 = rays[ray * 6 + 5];

    // ============ sphere tracing (warp-wide early break over 16 rays) =======
    float cd = kNEAR;
    bool hit = false;
#pragma unroll 1
    for (int it = 0; it < kITERS; ++it) {
        float x0 = __fadd_rn(ro0, __fmul_rn(rd0, cd));
        float x1 = __fadd_rn(ro1, __fmul_rn(rd1, cd));
        float x2 = __fadd_rn(ro2, __fmul_rn(rd2, cd));
        float XA[3], XB[3];
        bcast2(x0, x1, x2, lane, XA, XB);
        float dist = sdf_approx(XA, XB, w1pack, sBH, bwv, lane) + bb3;
        bool h = (dist < kEPS) && (cd >= kNEAR) && (cd <= kFAR);
        hit = hit || h;
        if (!hit) cd += dist;
        if (__all_sync(0xffffffffu, hit)) break;
    }

    // ============ reflectance MLP (scalar, cheap) ============
    float p0 = __fadd_rn(ro0, __fmul_rn(rd0, cd));
    float p1 = __fadd_rn(ro1, __fmul_rn(rd1, cd));
    float p2 = __fadd_rn(ro2, __fmul_rn(rd2, cd));
    float rgb0 = smem[OFF_MISC + 0], rgb1 = smem[OFF_MISC + 1], rgb2 = smem[OFF_MISC + 2];
    {
        const float4* r1a = reinterpret_cast<const float4*>(smem + OFF_R1A);
        const float4* r1b = reinterpret_cast<const float4*>(smem + OFF_R1B);
        const float4* r2v = reinterpret_cast<const float4*>(smem + OFF_R2);
#pragma unroll 4
        for (int j = 0; j < HN; ++j) {
            float4 a = r1a[j];
            float4 b = r1b[j];
            float hv = fmaf(a.x, p0, fmaf(a.y, p1, fmaf(a.z, p2,
                       fmaf(a.w, rd0, fmaf(b.x, rd1, fmaf(b.y, rd2, b.z))))));
            hv = fmaxf(hv, 0.0f);
            float4 w = r2v[j];
            rgb0 = fmaf(hv, w.x, rgb0);
            rgb1 = fmaf(hv, w.y, rgb1);
            rgb2 = fmaf(hv, w.z, rgb2);
        }
    }
    if (!hit) { rgb0 = 0.0f; rgb1 = 0.0f; rgb2 = 0.0f; }

    // ============ tube-point scan (approx ranking) ============
    float m_ap = __int_as_float(0x7f800000);
    int   bi   = 0;
#pragma unroll 1
    for (int i = 0; i <= kTP; ++i) {
        float t = kSTEP * (float)i;
        float x0 = __fadd_rn(ro0, __fmul_rn(rd0, t));
        float x1 = __fadd_rn(ro1, __fmul_rn(rd1, t));
        float x2 = __fadd_rn(ro2, __fmul_rn(rd2, t));
        float XA[3], XB[3];
        bcast2(x0, x1, x2, lane, XA, XB);
        float sd = sdf_approx(XA, XB, w1pack, sBH, bwv, lane);
        if (sd < m_ap) { m_ap = sd; bi = i; }
    }
    // precise re-eval at the per-ray argmin point (tput == curr_min identity)
    float m;
    {
        float tb = kSTEP * (float)bi;
        float x0 = __fadd_rn(ro0, __fmul_rn(rd0, tb));
        float x1 = __fadd_rn(ro1, __fmul_rn(rd1, tb));
        float x2 = __fadd_rn(ro2, __fmul_rn(rd2, tb));
        float XA[3], XB[3];
        bcast2(x0, x1, x2, lane, XA, XB);
        m = sdf_precise(XA, XB, w1pack, sBH, bwv, lane) + bb3;
    }

    if (active) {
        float4 o;
        o.x = rgb0; o.y = rgb1; o.z = rgb2; o.w = -kALPHA * m;
        reinterpret_cast<float4*>(out)[ray] = o;
    }
}

extern "C" void kernel_launch(void* const* d_in, const int* in_sizes, int n_in,
                              void* d_out, int out_size) {
    const float* rays = (const float*)d_in[0];
    const float* W1   = (const float*)d_in[1];
    const float* b1   = (const float*)d_in[2];
    const float* W2   = (const float*)d_in[3];
    const float* b2   = (const float*)d_in[4];
    const float* W3   = (const float*)d_in[5];
    const float* b3   = (const float*)d_in[6];
    const float* R1   = (const float*)d_in[7];
    const float* rb1  = (const float*)d_in[8];
    const float* R2   = (const float*)d_in[9];
    const float* rb2  = (const float*)d_in[10];
    float* out = (float*)d_out;

    const int n = in_sizes[0] / 6;

    sdf_prep_kernel<<<16, 128>>>(W2);

    cudaFuncSetAttribute(sdf_mma_kernel,
                         cudaFuncAttributeMaxDynamicSharedMemorySize, SMEM_BYTES);

    const int grid = (n + 63) / 64;
    sdf_mma_kernel<<<grid, 128, SMEM_BYTES>>>(
        rays, W1, b1, b2, W3, b3, R1, rb1, R2, rb2, out, n);
}

// round 12
// speedup vs baseline: 1.1863x; 1.1863x over previous
#include <cuda_runtime.h>
#include <cuda_fp16.h>
#include <cstdint>

// ---------------------------------------------------------------------------
// Neural-SDF ray march + tube min + reflectance.
// Warp-cooperative, 32 rays/warp; each SDF eval = 32x128x128 GEMM via
// mma.sync.m16n8k16 f16 (256 mma). Layer-2 in four n-quarters (C=32 regs) so
// the kernel fits 128 regs -> __launch_bounds__(128,4) = 16 warps/SM.
//   * march + tube scan: 1-term fp16
//   * column-3: ONE precise 3-term eval per ray at the approx argmin;
//     B_lo residuals streamed from a __device__ global (L2-resident)
// ---------------------------------------------------------------------------

#define DINL __device__ __forceinline__

namespace {
constexpr int   HN     = 128;
constexpr float kNEAR  = 0.2f;
constexpr float kFAR   = 2.0f;
constexpr float kALPHA = 100.0f;
constexpr float kEPS   = 0.005f;
constexpr int   kITERS = 32;
constexpr int   kTP    = 32;
constexpr float kSTEP  = 0.0634765625f;  // (2 + 0.5*(2/32))/32, exact fp32

// shared memory layout (float offsets)
constexpr int OFF_BH   = 0;        // 8192 floats: W2 fp16-hi frag pack
constexpr int OFF_W1   = 8192;     // float4[128]: (W1[0][k],W1[1][k],W1[2][k],b1[k])
constexpr int OFF_BW   = 8704;     // float2[128]: (b2[n], W3[n])
constexpr int OFF_R1A  = 8960;     // float4[128]: R1 rows 0..3
constexpr int OFF_R1B  = 9472;     // float4[128]: (R1[4][j],R1[5][j],rb1[j],0)
constexpr int OFF_R2   = 9984;     // float4[128]: (R2[j][0..2],0)
constexpr int OFF_MISC = 10496;    // rb2[0..2], b3
constexpr int SMEM_FLOATS = 10500;
constexpr int SMEM_BYTES  = SMEM_FLOATS * 4;
}  // namespace

// W2 fp16 hi/lo in mma-fragment pack, staged once by the prep kernel.
__device__ float4 g_BH[2048];
__device__ float4 g_BL[2048];

DINL uint32_t pk16(float e0, float e1) {
    uint32_t d;
    asm("cvt.rn.f16x2.f32 %0, %1, %2;" : "=r"(d) : "f"(e1), "f"(e0));
    return d;
}
DINL uint32_t pk16relu(float e0, float e1) {
    uint32_t d;
    asm("cvt.rn.relu.f16x2.f32 %0, %1, %2;" : "=r"(d) : "f"(e1), "f"(e0));
    return d;
}
DINL float f16_round(float x) { return __half2float(__float2half_rn(x)); }

DINL void mma16_acc(float c[4], uint32_t a0, uint32_t a1, uint32_t a2,
                    uint32_t a3, uint32_t b0, uint32_t b1) {
    asm volatile(
        "mma.sync.aligned.m16n8k16.row.col.f32.f16.f16.f32 "
        "{%0,%1,%2,%3},{%4,%5,%6,%7},{%8,%9},{%0,%1,%2,%3};"
        : "+f"(c[0]), "+f"(c[1]), "+f"(c[2]), "+f"(c[3])
        : "r"(a0), "r"(a1), "r"(a2), "r"(a3), "r"(b0), "r"(b1));
}
DINL void mma16_zero(float c[4], uint32_t a0, uint32_t a1, uint32_t a2,
                     uint32_t a3, uint32_t b0, uint32_t b1) {
    float z = 0.0f;
    asm volatile(
        "mma.sync.aligned.m16n8k16.row.col.f32.f16.f16.f32 "
        "{%0,%1,%2,%3},{%4,%5,%6,%7},{%8,%9},{%10,%10,%10,%10};"
        : "=f"(c[0]), "=f"(c[1]), "=f"(c[2]), "=f"(c[3])
        : "r"(a0), "r"(a1), "r"(a2), "r"(a3), "r"(b0), "r"(b1), "f"(z));
}

// lane 4g+c exposes ray g+8c; owner lane l fetches from 4*(l&7)+(l>>3)
DINL float expose_own(float p0, float p1, float p2, float p3, int lane) {
    p0 += __shfl_xor_sync(0xffffffffu, p0, 1);
    p0 += __shfl_xor_sync(0xffffffffu, p0, 2);
    p1 += __shfl_xor_sync(0xffffffffu, p1, 1);
    p1 += __shfl_xor_sync(0xffffffffu, p1, 2);
    p2 += __shfl_xor_sync(0xffffffffu, p2, 1);
    p2 += __shfl_xor_sync(0xffffffffu, p2, 2);
    p3 += __shfl_xor_sync(0xffffffffu, p3, 1);
    p3 += __shfl_xor_sync(0xffffffffu, p3, 2);
    const int t4 = lane & 3;
    float expose = (t4 == 0) ? p0 : (t4 == 1) ? p1 : (t4 == 2) ? p2 : p3;
    int src = ((lane & 7) << 2) | (lane >> 3);
    return __shfl_sync(0xffffffffu, expose, src);
}

// --------------------- approx eval: 1-term fp16 (256 mma) --------------------
// X*[c] = coords of warp-ray (lane>>2)+8c. Returns own-ray value (WITHOUT b3).
DINL float sdf_approx(const float* X0, const float* X1, const float* X2,
                      const float4* __restrict__ w1pack,
                      const float4* __restrict__ sBH,
                      const float4* __restrict__ bwv, int lane) {
    const int t4 = lane & 3;

    // layer-1: pack A_hi for all k-chunks (relu fused into cvt)
    uint32_t Ah[64];
#pragma unroll
    for (int kc = 0; kc < 8; ++kc) {
        const int k0 = kc * 16 + 2 * t4;
        float4 w0 = w1pack[k0];
        float4 w1 = w1pack[k0 + 1];
        float4 w8 = w1pack[k0 + 8];
        float4 w9 = w1pack[k0 + 9];
#pragma unroll
        for (int mt = 0; mt < 2; ++mt) {
            const int cA = 2 * mt, cB = 2 * mt + 1;
            float h0A = fmaf(w0.x, X0[cA], fmaf(w0.y, X1[cA], fmaf(w0.z, X2[cA], w0.w)));
            float h1A = fmaf(w1.x, X0[cA], fmaf(w1.y, X1[cA], fmaf(w1.z, X2[cA], w1.w)));
            float h8A = fmaf(w8.x, X0[cA], fmaf(w8.y, X1[cA], fmaf(w8.z, X2[cA], w8.w)));
            float h9A = fmaf(w9.x, X0[cA], fmaf(w9.y, X1[cA], fmaf(w9.z, X2[cA], w9.w)));
            float h0B = fmaf(w0.x, X0[cB], fmaf(w0.y, X1[cB], fmaf(w0.z, X2[cB], w0.w)));
            float h1B = fmaf(w1.x, X0[cB], fmaf(w1.y, X1[cB], fmaf(w1.z, X2[cB], w1.w)));
            float h8B = fmaf(w8.x, X0[cB], fmaf(w8.y, X1[cB], fmaf(w8.z, X2[cB], w8.w)));
            float h9B = fmaf(w9.x, X0[cB], fmaf(w9.y, X1[cB], fmaf(w9.z, X2[cB], w9.w)));
            Ah[kc * 8 + mt * 4 + 0] = pk16relu(h0A, h1A);
            Ah[kc * 8 + mt * 4 + 1] = pk16relu(h0B, h1B);
            Ah[kc * 8 + mt * 4 + 2] = pk16relu(h8A, h9A);
            Ah[kc * 8 + mt * 4 + 3] = pk16relu(h8B, h9B);
        }
    }

    // layer-2 + epilogue in four n-quarters (C = 32 regs live)
    float p0 = 0.f, p1 = 0.f, p2 = 0.f, p3 = 0.f;
#pragma unroll
    for (int q = 0; q < 4; ++q) {
        float C[2][4][4];
#pragma unroll
        for (int kc = 0; kc < 8; ++kc) {
            const uint32_t* a = Ah + kc * 8;
            const float4* bq = sBH + (kc * 8 + q * 2) * 32 + lane;
#pragma unroll
            for (int p = 0; p < 2; ++p) {
                float4 B = bq[p * 32];
                uint32_t b0 = __float_as_uint(B.x), b1 = __float_as_uint(B.y);
                uint32_t b2r = __float_as_uint(B.z), b3r = __float_as_uint(B.w);
                if (kc == 0) {
                    mma16_zero(C[0][2 * p],     a[0], a[1], a[2], a[3], b0, b1);
                    mma16_zero(C[1][2 * p],     a[4], a[5], a[6], a[7], b0, b1);
                    mma16_zero(C[0][2 * p + 1], a[0], a[1], a[2], a[3], b2r, b3r);
                    mma16_zero(C[1][2 * p + 1], a[4], a[5], a[6], a[7], b2r, b3r);
                } else {
                    mma16_acc(C[0][2 * p],     a[0], a[1], a[2], a[3], b0, b1);
                    mma16_acc(C[1][2 * p],     a[4], a[5], a[6], a[7], b0, b1);
                    mma16_acc(C[0][2 * p + 1], a[0], a[1], a[2], a[3], b2r, b3r);
                    mma16_acc(C[1][2 * p + 1], a[4], a[5], a[6], a[7], b2r, b3r);
                }
            }
        }
#pragma unroll
        for (int j = 0; j < 4; ++j) {
            float4 bw = bwv[(q * 4 + j) * 4 + t4];
            p0 = fmaf(fmaxf(C[0][j][0] + bw.x, 0.f), bw.y, p0);
            p0 = fmaf(fmaxf(C[0][j][1] + bw.z, 0.f), bw.w, p0);
            p1 = fmaf(fmaxf(C[0][j][2] + bw.x, 0.f), bw.y, p1);
            p1 = fmaf(fmaxf(C[0][j][3] + bw.z, 0.f), bw.w, p1);
            p2 = fmaf(fmaxf(C[1][j][0] + bw.x, 0.f), bw.y, p2);
            p2 = fmaf(fmaxf(C[1][j][1] + bw.z, 0.f), bw.w, p2);
            p3 = fmaf(fmaxf(C[1][j][2] + bw.x, 0.f), bw.y, p3);
            p3 = fmaf(fmaxf(C[1][j][3] + bw.z, 0.f), bw.w, p3);
        }
    }
    return expose_own(p0, p1, p2, p3, lane);
}

// --------------- precise eval: 3-term fp16 (768 mma, once per ray) -----------
// Quarter-split; layer-1 recomputed per quarter; B_lo streamed from g_BL.
DINL float sdf_precise(const float* X0, const float* X1, const float* X2,
                       const float4* __restrict__ w1pack,
                       const float4* __restrict__ sBH,
                       const float4* __restrict__ bwv, int lane) {
    const int t4 = lane & 3;
    float p0 = 0.f, p1 = 0.f, p2 = 0.f, p3 = 0.f;
#pragma unroll 1
    for (int q = 0; q < 4; ++q) {
        float C[2][4][4];
#pragma unroll 1
        for (int kc = 0; kc < 8; ++kc) {
            const int k0 = kc * 16 + 2 * t4;
            float4 w0 = w1pack[k0];
            float4 w1 = w1pack[k0 + 1];
            float4 w8 = w1pack[k0 + 8];
            float4 w9 = w1pack[k0 + 9];
            uint32_t ahi[8], alo[8];
#pragma unroll
            for (int mt = 0; mt < 2; ++mt) {
                const int cA = 2 * mt, cB = 2 * mt + 1;
                float h[4][2], r[4][2];
                h[0][0] = fmaxf(fmaf(w0.x, X0[cA], fmaf(w0.y, X1[cA], fmaf(w0.z, X2[cA], w0.w))), 0.f);
                h[1][0] = fmaxf(fmaf(w1.x, X0[cA], fmaf(w1.y, X1[cA], fmaf(w1.z, X2[cA], w1.w))), 0.f);
                h[2][0] = fmaxf(fmaf(w8.x, X0[cA], fmaf(w8.y, X1[cA], fmaf(w8.z, X2[cA], w8.w))), 0.f);
                h[3][0] = fmaxf(fmaf(w9.x, X0[cA], fmaf(w9.y, X1[cA], fmaf(w9.z, X2[cA], w9.w))), 0.f);
                h[0][1] = fmaxf(fmaf(w0.x, X0[cB], fmaf(w0.y, X1[cB], fmaf(w0.z, X2[cB], w0.w))), 0.f);
                h[1][1] = fmaxf(fmaf(w1.x, X0[cB], fmaf(w1.y, X1[cB], fmaf(w1.z, X2[cB], w1.w))), 0.f);
                h[2][1] = fmaxf(fmaf(w8.x, X0[cB], fmaf(w8.y, X1[cB], fmaf(w8.z, X2[cB], w8.w))), 0.f);
                h[3][1] = fmaxf(fmaf(w9.x, X0[cB], fmaf(w9.y, X1[cB], fmaf(w9.z, X2[cB], w9.w))), 0.f);
#pragma unroll
                for (int s = 0; s < 4; ++s) {
                    r[s][0] = h[s][0] - f16_round(h[s][0]);
                    r[s][1] = h[s][1] - f16_round(h[s][1]);
                }
                ahi[mt * 4 + 0] = pk16(h[0][0], h[1][0]);
                ahi[mt * 4 + 1] = pk16(h[0][1], h[1][1]);
                ahi[mt * 4 + 2] = pk16(h[2][0], h[3][0]);
                ahi[mt * 4 + 3] = pk16(h[2][1], h[3][1]);
                alo[mt * 4 + 0] = pk16(r[0][0], r[1][0]);
                alo[mt * 4 + 1] = pk16(r[0][1], r[1][1]);
                alo[mt * 4 + 2] = pk16(r[2][0], r[3][0]);
                alo[mt * 4 + 3] = pk16(r[2][1], r[3][1]);
            }
            const float4* bqh = sBH + (kc * 8 + q * 2) * 32 + lane;
            const float4* bql = g_BL + (kc * 8 + q * 2) * 32 + lane;
#pragma unroll
            for (int p = 0; p < 2; ++p) {
                float4 BH = bqh[p * 32];
                float4 BL = bql[p * 32];
                uint32_t h0 = __float_as_uint(BH.x), h1 = __float_as_uint(BH.y);
                uint32_t h2 = __float_as_uint(BH.z), h3 = __float_as_uint(BH.w);
                uint32_t l0 = __float_as_uint(BL.x), l1 = __float_as_uint(BL.y);
                uint32_t l2 = __float_as_uint(BL.z), l3 = __float_as_uint(BL.w);
                if (kc == 0) {
                    mma16_zero(C[0][2 * p],     ahi[0], ahi[1], ahi[2], ahi[3], h0, h1);
                    mma16_zero(C[1][2 * p],     ahi[4], ahi[5], ahi[6], ahi[7], h0, h1);
                    mma16_zero(C[0][2 * p + 1], ahi[0], ahi[1], ahi[2], ahi[3], h2, h3);
                    mma16_zero(C[1][2 * p + 1], ahi[4], ahi[5], ahi[6], ahi[7], h2, h3);
                } else {
                    mma16_acc(C[0][2 * p],     ahi[0], ahi[1], ahi[2], ahi[3], h0, h1);
                    mma16_acc(C[1][2 * p],     ahi[4], ahi[5], ahi[6], ahi[7], h0, h1);
                    mma16_acc(C[0][2 * p + 1], ahi[0], ahi[1], ahi[2], ahi[3], h2, h3);
                    mma16_acc(C[1][2 * p + 1], ahi[4], ahi[5], ahi[6], ahi[7], h2, h3);
                }
                mma16_acc(C[0][2 * p],     alo[0], alo[1], alo[2], alo[3], h0, h1);
                mma16_acc(C[1][2 * p],     alo[4], alo[5], alo[6], alo[7], h0, h1);
                mma16_acc(C[0][2 * p + 1], alo[0], alo[1], alo[2], alo[3], h2, h3);
                mma16_acc(C[1][2 * p + 1], alo[4], alo[5], alo[6], alo[7], h2, h3);
                mma16_acc(C[0][2 * p],     ahi[0], ahi[1], ahi[2], ahi[3], l0, l1);
                mma16_acc(C[1][2 * p],     ahi[4], ahi[5], ahi[6], ahi[7], l0, l1);
                mma16_acc(C[0][2 * p + 1], ahi[0], ahi[1], ahi[2], ahi[3], l2, l3);
                mma16_acc(C[1][2 * p + 1], ahi[4], ahi[5], ahi[6], ahi[7], l2, l3);
            }
        }
#pragma unroll
        for (int j = 0; j < 4; ++j) {
            float4 bw = bwv[(q * 4 + j) * 4 + t4];
            p0 = fmaf(fmaxf(C[0][j][0] + bw.x, 0.f), bw.y, p0);
            p0 = fmaf(fmaxf(C[0][j][1] + bw.z, 0.f), bw.w, p0);
            p1 = fmaf(fmaxf(C[0][j][2] + bw.x, 0.f), bw.y, p1);
            p1 = fmaf(fmaxf(C[0][j][3] + bw.z, 0.f), bw.w, p1);
            p2 = fmaf(fmaxf(C[1][j][0] + bw.x, 0.f), bw.y, p2);
            p2 = fmaf(fmaxf(C[1][j][1] + bw.z, 0.f), bw.w, p2);
            p3 = fmaf(fmaxf(C[1][j][2] + bw.x, 0.f), bw.y, p3);
            p3 = fmaf(fmaxf(C[1][j][3] + bw.z, 0.f), bw.w, p3);
        }
    }
    return expose_own(p0, p1, p2, p3, lane);
}

DINL void bcast_X(float x0, float x1, float x2, int lane,
                  float* X0, float* X1, float* X2) {
#pragma unroll
    for (int c = 0; c < 4; ++c) {
        int src = (lane >> 2) + 8 * c;
        X0[c] = __shfl_sync(0xffffffffu, x0, src);
        X1[c] = __shfl_sync(0xffffffffu, x1, src);
        X2[c] = __shfl_sync(0xffffffffu, x2, src);
    }
}

// ------------------------- prep kernel (B pack) ------------------------------
// entry idx: (kc*8 + nbp)*32 + l; t=l&3, g=l>>2, k0=16kc+2t, n0=16nbp+g, n1=n0+8
__global__ void sdf_prep_kernel(const float* __restrict__ W2) {
    int idx = blockIdx.x * blockDim.x + threadIdx.x;
    if (idx >= 2048) return;
    int l = idx & 31, nbp = (idx >> 5) & 7, kc = idx >> 8;
    int t = l & 3, g = l >> 2;
    int n0 = nbp * 16 + g, n1 = n0 + 8;
    int k0 = kc * 16 + 2 * t;
    float a00 = W2[k0 * HN + n0],       a01 = W2[(k0 + 1) * HN + n0];
    float a08 = W2[(k0 + 8) * HN + n0], a09 = W2[(k0 + 9) * HN + n0];
    float b00 = W2[k0 * HN + n1],       b01 = W2[(k0 + 1) * HN + n1];
    float b08 = W2[(k0 + 8) * HN + n1], b09 = W2[(k0 + 9) * HN + n1];
    float4 vh, vl;
    vh.x = __uint_as_float(pk16(a00, a01));
    vh.y = __uint_as_float(pk16(a08, a09));
    vh.z = __uint_as_float(pk16(b00, b01));
    vh.w = __uint_as_float(pk16(b08, b09));
    vl.x = __uint_as_float(pk16(a00 - f16_round(a00), a01 - f16_round(a01)));
    vl.y = __uint_as_float(pk16(a08 - f16_round(a08), a09 - f16_round(a09)));
    vl.z = __uint_as_float(pk16(b00 - f16_round(b00), b01 - f16_round(b01)));
    vl.w = __uint_as_float(pk16(b08 - f16_round(b08), b09 - f16_round(b09)));
    g_BH[idx] = vh;
    g_BL[idx] = vl;
}

// ------------------------------- main kernel ---------------------------------
__global__ void __launch_bounds__(128, 4) sdf_mma_kernel(
    const float* __restrict__ rays,
    const float* __restrict__ W1, const float* __restrict__ b1,
    const float* __restrict__ b2,
    const float* __restrict__ W3, const float* __restrict__ b3,
    const float* __restrict__ R1, const float* __restrict__ rb1,
    const float* __restrict__ R2, const float* __restrict__ rb2,
    float* __restrict__ out, int n)
{
    extern __shared__ float smem[];
    const int tid = threadIdx.x;
    const int lane = tid & 31;

    {   // copy pre-packed B_hi into smem
        float4* dst = reinterpret_cast<float4*>(smem + OFF_BH);
        for (int i = tid; i < 2048; i += 128) dst[i] = g_BH[i];
    }
    {   // small weights
        float4* w1v  = reinterpret_cast<float4*>(smem + OFF_W1);
        float2* bwv2 = reinterpret_cast<float2*>(smem + OFF_BW);
        float4* r1av = reinterpret_cast<float4*>(smem + OFF_R1A);
        float4* r1bv = reinterpret_cast<float4*>(smem + OFF_R1B);
        float4* r2v  = reinterpret_cast<float4*>(smem + OFF_R2);
        for (int j = tid; j < HN; j += 128) {
            w1v[j]  = make_float4(W1[j], W1[HN + j], W1[2 * HN + j], b1[j]);
            bwv2[j] = make_float2(b2[j], W3[j]);
            r1av[j] = make_float4(R1[j], R1[HN + j], R1[2 * HN + j], R1[3 * HN + j]);
            r1bv[j] = make_float4(R1[4 * HN + j], R1[5 * HN + j], rb1[j], 0.0f);
            r2v[j]  = make_float4(R2[3 * j], R2[3 * j + 1], R2[3 * j + 2], 0.0f);
        }
    }
    if (tid < 3) smem[OFF_MISC + tid] = rb2[tid];
    if (tid == 0) smem[OFF_MISC + 3] = b3[0];
    __syncthreads();

    const float4* w1pack = reinterpret_cast<const float4*>(smem + OFF_W1);
    const float4* sBH    = reinterpret_cast<const float4*>(smem + OFF_BH);
    const float4* bwv    = reinterpret_cast<const float4*>(smem + OFF_BW);
    const float bb3 = smem[OFF_MISC + 3];

    int ray = blockIdx.x * 128 + tid;
    const bool active = ray < n;
    if (!active) ray = n - 1;
    const float ro0 = rays[ray * 6 + 0], ro1 = rays[ray * 6 + 1], ro2 = rays[ray * 6 + 2];
    const float rd0 = rays[ray * 6 + 3], rd1 = rays[ray * 6 + 4], rd2 = rays[ray * 6 + 5];

    // ============ sphere tracing (warp-wide early break) ============
    float cd = kNEAR;
    bool hit = false;
#pragma unroll 1
    for (int it = 0; it < kITERS; ++it) {
        float x0 = __fadd_rn(ro0, __fmul_rn(rd0, cd));
        float x1 = __fadd_rn(ro1, __fmul_rn(rd1, cd));
        float x2 = __fadd_rn(ro2, __fmul_rn(rd2, cd));
        float X0[4], X1[4], X2[4];
        bcast_X(x0, x1, x2, lane, X0, X1, X2);
        float dist = sdf_approx(X0, X1, X2, w1pack, sBH, bwv, lane) + bb3;
        bool h = (dist < kEPS) && (cd >= kNEAR) && (cd <= kFAR);
        hit = hit || h;
        if (!hit) cd += dist;
        if (__all_sync(0xffffffffu, hit)) break;
    }

    // ============ reflectance MLP (scalar, cheap) ============
    float p0 = __fadd_rn(ro0, __fmul_rn(rd0, cd));
    float p1 = __fadd_rn(ro1, __fmul_rn(rd1, cd));
    float p2 = __fadd_rn(ro2, __fmul_rn(rd2, cd));
    float rgb0 = smem[OFF_MISC + 0], rgb1 = smem[OFF_MISC + 1], rgb2 = smem[OFF_MISC + 2];
    {
        const float4* r1a = reinterpret_cast<const float4*>(smem + OFF_R1A);
        const float4* r1b = reinterpret_cast<const float4*>(smem + OFF_R1B);
        const float4* r2v = reinterpret_cast<const float4*>(smem + OFF_R2);
#pragma unroll 4
        for (int j = 0; j < HN; ++j) {
            float4 a = r1a[j];
            float4 b = r1b[j];
            float hv = fmaf(a.x, p0, fmaf(a.y, p1, fmaf(a.z, p2,
                       fmaf(a.w, rd0, fmaf(b.x, rd1, fmaf(b.y, rd2, b.z))))));
            hv = fmaxf(hv, 0.0f);
            float4 w = r2v[j];
            rgb0 = fmaf(hv, w.x, rgb0);
            rgb1 = fmaf(hv, w.y, rgb1);
            rgb2 = fmaf(hv, w.z, rgb2);
        }
    }
    if (!hit) { rgb0 = 0.0f; rgb1 = 0.0f; rgb2 = 0.0f; }

    // ============ tube-point scan (approx ranking) ============
    float m_ap = __int_as_float(0x7f800000);
    int   bi   = 0;
#pragma unroll 1
    for (int i = 0; i <= kTP; ++i) {
        float t = kSTEP * (float)i;
        float x0 = __fadd_rn(ro0, __fmul_rn(rd0, t));
        float x1 = __fadd_rn(ro1, __fmul_rn(rd1, t));
        float x2 = __fadd_rn(ro2, __fmul_rn(rd2, t));
        float X0[4], X1[4], X2[4];
        bcast_X(x0, x1, x2, lane, X0, X1, X2);
        float sd = sdf_approx(X0, X1, X2, w1pack, sBH, bwv, lane);
        if (sd < m_ap) { m_ap = sd; bi = i; }
    }
    // precise re-eval at the per-ray argmin point (tput == curr_min identity)
    float m;
    {
        float tb = kSTEP * (float)bi;
        float x0 = __fadd_rn(ro0, __fmul_rn(rd0, tb));
        float x1 = __fadd_rn(ro1, __fmul_rn(rd1, tb));
        float x2 = __fadd_rn(ro2, __fmul_rn(rd2, tb));
        float X0[4], X1[4], X2[4];
        bcast_X(x0, x1, x2, lane, X0, X1, X2);
        m = sdf_precise(X0, X1, X2, w1pack, sBH, bwv, lane) + bb3;
    }

    if (active) {
        float4 o;
        o.x = rgb0; o.y = rgb1; o.z = rgb2; o.w = -kALPHA * m;
        reinterpret_cast<float4*>(out)[ray] = o;
    }
}

extern "C" void kernel_launch(void* const* d_in, const int* in_sizes, int n_in,
                              void* d_out, int out_size) {
    const float* rays = (const float*)d_in[0];
    const float* W1   = (const float*)d_in[1];
    const float* b1   = (const float*)d_in[2];
    const float* W2   = (const float*)d_in[3];
    const float* b2   = (const float*)d_in[4];
    const float* W3   = (const float*)d_in[5];
    const float* b3   = (const float*)d_in[6];
    const float* R1   = (const float*)d_in[7];
    const float* rb1  = (const float*)d_in[8];
    const float* R2   = (const float*)d_in[9];
    const float* rb2  = (const float*)d_in[10];
    float* out = (float*)d_out;

    const int n = in_sizes[0] / 6;

    sdf_prep_kernel<<<16, 128>>>(W2);

    cudaFuncSetAttribute(sdf_mma_kernel,
                         cudaFuncAttributeMaxDynamicSharedMemorySize, SMEM_BYTES);

    const int grid = (n + 127) / 128;
    sdf_mma_kernel<<<grid, 128, SMEM_BYTES>>>(
        rays, W1, b1, b2, W3, b3, R1, rb1, R2, rb2, out, n);
}